// round 5
// baseline (speedup 1.0000x reference)
#include <cuda_runtime.h>
#include <cuda_bf16.h>
#include <math.h>

#define BB   4096
#define FF   24
#define VV   1000
#define DD   32
#define FD   768          // F*D
#define COMB 1536         // 2*F*D
#define H0N  1024
#define H1N  512
#define RED  8
#define EPSV 1e-5f
#define NSTG 3

// ---------------- device scratch ----------------
__device__ __align__(16) float g_E2r[2 * BB * FD];   // tf32-rounded (GEMM A)
__device__ __align__(16) float g_E2x[2 * BB * FD];   // exact (epilogue multiply)
__device__ __align__(16) float g_WT[FD * FD];        // tf32-rounded, diag zeroed
__device__ __align__(16) float g_comb[BB * COMB];    // tf32-rounded
__device__ __align__(16) float g_h0[BB * H0N];       // exact (for BN stats)
__device__ __align__(16) float g_h0t[BB * H0N];      // relu(bn(h0)) tf32-rounded
__device__ __align__(16) float g_h1[BB * H1N];
__device__ __align__(16) float g_w0t[COMB * H0N];    // tf32-rounded weights
__device__ __align__(16) float g_w1t[H0N * H1N];
__device__ float g_lin[BB];
__device__ float g_scale0[H0N], g_shift0[H0N];
__device__ float g_scale1[H1N], g_shift1[H1N];

#define CVT_TF32(u, f) asm("cvt.rna.tf32.f32 %0, %1;" : "=r"(u) : "f"(f))

__device__ __forceinline__ float tf32r(float f) {
    unsigned u; CVT_TF32(u, f); return __uint_as_float(u);
}

__device__ __forceinline__ void cp16(unsigned dst, const void* src) {
    asm volatile("cp.async.cg.shared.global [%0], [%1], 16;" :: "r"(dst), "l"(src));
}

// ---------------- K0: W -> WT (diag zeroed, tf32-rounded) ------------------
__global__ void transposeW_kernel(const float* __restrict__ W, float* __restrict__ WT) {
    int o = blockIdx.x * 256 + threadIdx.x;
    int ik = o % FD, jl = o / FD;
    int i = ik >> 5, k = ik & 31, j = jl >> 5, l = jl & 31;
    float v = (i == j) ? 0.f : W[(((i * FF + j) * DD + k) * DD) + l];
    WT[o] = tf32r(v);
}

// ---------------- weight tf32 pre-round ------------------------------------
__global__ void cvt_kernel(const float* __restrict__ src, float* __restrict__ dst) {
    int i = (blockIdx.x * 256 + threadIdx.x) * 4;
    float4 v = *(const float4*)&src[i];
    v.x = tf32r(v.x); v.y = tf32r(v.y); v.z = tf32r(v.z); v.w = tf32r(v.w);
    *(float4*)&dst[i] = v;
}

// ---------------- K1: gather + linear + SENet -----------------------------
__global__ void gather_se_kernel(const int* __restrict__ x,
                                 const float* __restrict__ emb,
                                 const float* __restrict__ lint,
                                 const float* __restrict__ sw1,
                                 const float* __restrict__ sw2,
                                 float* __restrict__ E2r,
                                 float* __restrict__ E2x,
                                 float* __restrict__ linout) {
    int b = blockIdx.x;
    int t = threadIdx.x;
    __shared__ int   xs[FF];
    __shared__ float es[FD];
    __shared__ float Zs[FF], hid[RED], As[FF], linp[FF];

    if (t < FF) xs[t] = x[b * FF + t];
    __syncthreads();

    #pragma unroll
    for (int r = 0; r < 3; r++) {
        int ik = t + r * 256;
        int f = ik >> 5, d = ik & 31;
        es[ik] = emb[((long)f * VV + xs[f]) * DD + d];
    }
    if (t < FF) linp[t] = lint[(long)t * VV + xs[t]];
    __syncthreads();

    int w = t >> 5, lane = t & 31;
    #pragma unroll
    for (int ff = 0; ff < 3; ff++) {
        int f = w * 3 + ff;
        float v = es[f * 32 + lane];
        #pragma unroll
        for (int o = 16; o > 0; o >>= 1) v += __shfl_xor_sync(0xffffffffu, v, o);
        if (lane == 0) Zs[f] = v * (1.f / 32.f);
    }
    __syncthreads();
    if (t < RED) {
        float s = 0.f;
        #pragma unroll
        for (int f = 0; f < FF; f++) s += Zs[f] * sw1[t * FF + f];
        hid[t] = fmaxf(s, 0.f);
    }
    __syncthreads();
    if (t < FF) {
        float s = 0.f;
        #pragma unroll
        for (int r = 0; r < RED; r++) s += hid[r] * sw2[t * RED + r];
        As[t] = 1.f / (1.f + expf(-s));
    }
    if (t == 0) {
        float s = 0.f;
        #pragma unroll
        for (int f = 0; f < FF; f++) s += linp[f];
        linout[b] = s;
    }
    __syncthreads();

    #pragma unroll
    for (int r = 0; r < 3; r++) {
        int ik = t + r * 256;
        int f = ik >> 5;
        float e = es[ik];
        float ae = As[f] * e;
        E2x[(long)b * FD + ik] = e;
        E2x[(long)(BB + b) * FD + ik] = ae;
        E2r[(long)b * FD + ik] = tf32r(e);
        E2r[(long)(BB + b) * FD + ik] = tf32r(ae);
    }
}

// ---------------- tf32 tensor-core GEMM v3 ---------------------------------
// 256 thr = 8 warps (4m x 2n); block 128x128; warp 32x64; ktile 16.
// 3-stage cp.async pipeline; A smem XOR-swizzled; operands pre-rounded tf32.
template <bool BIAS, bool COMBINE>
__global__ void __launch_bounds__(256, 2)
tf32gemm3_kernel(const float* __restrict__ A, const float* __restrict__ Bm,
                 float* __restrict__ C, int M, int N, int K,
                 const float* __restrict__ bias, const float* __restrict__ E2x) {
    __shared__ __align__(16) unsigned Asm[NSTG * 2048];   // per stage: 128 rows x 16 (swizzled)
    __shared__ __align__(16) unsigned Bsm[NSTG * 2176];   // per stage: 16 rows x 136

    int t = threadIdx.x;
    int m0 = blockIdx.x * 128, n0 = blockIdx.y * 128;
    int wid = t >> 5, lane = t & 31;
    int wm = (wid & 3) * 32, wn = (wid >> 2) * 64;
    int r = lane >> 2, quad = lane & 3;

    float acc[2][8][4];
    #pragma unroll
    for (int mi = 0; mi < 2; mi++)
        #pragma unroll
        for (int ni = 0; ni < 8; ni++)
            #pragma unroll
            for (int c = 0; c < 4; c++) acc[mi][ni][c] = 0.f;

    // staging coords
    int am = t >> 1;              // 0..127 (A row)
    int ac = (t & 1) * 8;         // A word col: 0 or 8
    int bkr = t >> 4;             // 0..15 (B row)
    int bc = (t & 15) * 8;        // B word col

    const float* Ap = A + (long)(m0 + am) * K + ac;
    const float* Bp = Bm + (long)bkr * N + n0 + bc;
    unsigned abase = (unsigned)__cvta_generic_to_shared(Asm);
    unsigned bbase = (unsigned)__cvta_generic_to_shared(Bsm);
    int ch0 = (((ac >> 2) + 0) ^ (am >> 1)) & 3;
    int ch1 = (((ac >> 2) + 1) ^ (am >> 1)) & 3;
    unsigned adst0 = abase + (unsigned)(am * 16 + ch0 * 4) * 4u;
    unsigned adst1 = abase + (unsigned)(am * 16 + ch1 * 4) * 4u;
    unsigned bdst  = bbase + (unsigned)(bkr * 136 + bc) * 4u;

    int ntile = K >> 4;

    // fragment base offsets (words)
    int ia0[2], ia1[2];
    #pragma unroll
    for (int mi = 0; mi < 2; mi++) {
        int m  = wm + mi * 16 + r;
        int m2 = m + 8;
        ia0[mi] = m  * 16 + (((m  >> 1) & 3) << 2) + quad;   // c=quad (chunk 0 ^ swz)
        ia1[mi] = m2 * 16 + (((m2 >> 1) & 3) << 2) + quad;
    }
    int ib = quad * 136 + wn + r;

    // stage helper (macro-style lambda)
    auto stage = [&](int i, int s) {
        const float* as = Ap + i * 16;
        cp16(adst0 + s * 8192u, as);
        cp16(adst1 + s * 8192u, as + 4);
        const float* bs = Bp + (long)i * 16 * N;
        cp16(bdst + s * 8704u, bs);
        cp16(bdst + 16u + s * 8704u, bs + 4);
        asm volatile("cp.async.commit_group;");
    };

    stage(0, 0);
    stage(1, 1);

    for (int i = 0; i < ntile; i++) {
        asm volatile("cp.async.wait_group 1;");
        __syncthreads();
        if (i + 2 < ntile) stage(i + 2, (i + 2) % NSTG);

        const unsigned* asp = Asm + (i % NSTG) * 2048;
        const unsigned* bsp = Bsm + (i % NSTG) * 2176;

        #pragma unroll
        for (int ks = 0; ks < 16; ks += 8) {
            unsigned a[2][4];
            #pragma unroll
            for (int mi = 0; mi < 2; mi++) {
                a[mi][0] = asp[ia0[mi] ^ ks];
                a[mi][1] = asp[ia1[mi] ^ ks];
                a[mi][2] = asp[ia0[mi] ^ 4 ^ ks];
                a[mi][3] = asp[ia1[mi] ^ 4 ^ ks];
            }
            unsigned b[8][2];
            #pragma unroll
            for (int ni = 0; ni < 8; ni++) {
                b[ni][0] = bsp[ib + ks * 136 + ni * 8];
                b[ni][1] = bsp[ib + (ks + 4) * 136 + ni * 8];
            }
            #pragma unroll
            for (int mi = 0; mi < 2; mi++)
                #pragma unroll
                for (int ni = 0; ni < 8; ni++) {
                    asm volatile(
                        "mma.sync.aligned.m16n8k8.row.col.f32.tf32.tf32.f32 "
                        "{%0,%1,%2,%3}, {%4,%5,%6,%7}, {%8,%9}, {%0,%1,%2,%3};"
                        : "+f"(acc[mi][ni][0]), "+f"(acc[mi][ni][1]),
                          "+f"(acc[mi][ni][2]), "+f"(acc[mi][ni][3])
                        : "r"(a[mi][0]), "r"(a[mi][1]), "r"(a[mi][2]), "r"(a[mi][3]),
                          "r"(b[ni][0]), "r"(b[ni][1]));
                }
        }
        __syncthreads();
    }

    // ---- epilogue ----
    #pragma unroll
    for (int mi = 0; mi < 2; mi++) {
        #pragma unroll
        for (int ni = 0; ni < 8; ni++) {
            int row0 = m0 + wm + mi * 16 + r;
            int row1 = row0 + 8;
            int col  = n0 + wn + ni * 8 + 2 * quad;
            float2 v0 = make_float2(acc[mi][ni][0], acc[mi][ni][1]);
            float2 v1 = make_float2(acc[mi][ni][2], acc[mi][ni][3]);
            if (BIAS) {
                float b0v = bias[col], b1v = bias[col + 1];
                v0.x += b0v; v0.y += b1v;
                v1.x += b0v; v1.y += b1v;
            }
            if (COMBINE) {
                float2 e0 = *(const float2*)&E2x[(long)row0 * FD + col];
                float2 e1 = *(const float2*)&E2x[(long)row1 * FD + col];
                v0.x = tf32r(v0.x * e0.x); v0.y = tf32r(v0.y * e0.y);
                v1.x = tf32r(v1.x * e1.x); v1.y = tf32r(v1.y * e1.y);
                long br0 = (row0 < BB) ? row0 : (row0 - BB);
                long br1 = (row1 < BB) ? row1 : (row1 - BB);
                int  c0  = (row0 < BB) ? 0 : FD;
                int  c1  = (row1 < BB) ? 0 : FD;
                *(float2*)&C[br0 * (long)COMB + c0 + col] = v0;
                *(float2*)&C[br1 * (long)COMB + c1 + col] = v1;
            } else {
                *(float2*)&C[(long)row0 * N + col] = v0;
                *(float2*)&C[(long)row1 * N + col] = v1;
            }
        }
    }
}

// ---------------- BN stats -> scale/shift ----------------------------------
__global__ void bn_stats_kernel(const float* __restrict__ H, int N,
                                const float* __restrict__ g, const float* __restrict__ be,
                                float* __restrict__ scale, float* __restrict__ shift) {
    int lane = threadIdx.x & 31;
    int ty   = threadIdx.x >> 5;          // 0..15
    int col  = blockIdx.x * 32 + lane;
    float s = 0.f, sq = 0.f;
    for (int r = ty; r < BB; r += 16) {
        float v = H[(long)r * N + col];
        s += v; sq += v * v;
    }
    __shared__ float ss[16][33], sqs[16][33];
    ss[ty][lane] = s; sqs[ty][lane] = sq;
    __syncthreads();
    if (ty == 0) {
        #pragma unroll
        for (int i = 1; i < 16; i++) { s += ss[i][lane]; sq += sqs[i][lane]; }
        float mean = s * (1.f / BB);
        float var  = sq * (1.f / BB) - mean * mean;
        float sc   = g[col] * rsqrtf(var + EPSV);
        scale[col] = sc;
        shift[col] = be[col] - mean * sc;
    }
}

// ---------------- relu(bn(h0)) -> tf32-rounded -----------------------------
__global__ void bnrelu_kernel(const float* __restrict__ H,
                              const float* __restrict__ scale,
                              const float* __restrict__ shift,
                              float* __restrict__ Ht) {
    int i = (blockIdx.x * 256 + threadIdx.x) * 4;
    int col = i & (H0N - 1);
    float4 v = *(const float4*)&H[i];
    v.x = tf32r(fmaxf(0.f, v.x * scale[col + 0] + shift[col + 0]));
    v.y = tf32r(fmaxf(0.f, v.y * scale[col + 1] + shift[col + 1]));
    v.z = tf32r(fmaxf(0.f, v.z * scale[col + 2] + shift[col + 2]));
    v.w = tf32r(fmaxf(0.f, v.w * scale[col + 3] + shift[col + 3]));
    *(float4*)&Ht[i] = v;
}

// ---------------- final: BN+ReLU dot w2 + linear + sigmoid -----------------
__global__ void final_kernel(const float* __restrict__ H1,
                             const float* __restrict__ scale, const float* __restrict__ shift,
                             const float* __restrict__ w2, const float* __restrict__ b2,
                             const float* __restrict__ lin, const float* __restrict__ bias0,
                             float* __restrict__ out) {
    int warp = threadIdx.x >> 5, lane = threadIdx.x & 31;
    int row = blockIdx.x * 8 + warp;
    float acc = 0.f;
    #pragma unroll 4
    for (int k = lane; k < H1N; k += 32) {
        float v = H1[(long)row * H1N + k];
        v = fmaxf(0.f, v * scale[k] + shift[k]);
        acc += v * w2[k];
    }
    #pragma unroll
    for (int o = 16; o > 0; o >>= 1) acc += __shfl_xor_sync(0xffffffffu, acc, o);
    if (lane == 0) {
        float logit = acc + b2[0] + lin[row] + bias0[0];
        out[row] = 1.f / (1.f + expf(-logit));
    }
}

// ---------------------------------------------------------------------------
extern "C" void kernel_launch(void* const* d_in, const int* in_sizes, int n_in,
                              void* d_out, int out_size) {
    const int*   x    = (const int*)d_in[0];
    const float* emb  = (const float*)d_in[1];
    const float* lint = (const float*)d_in[2];
    const float* bias = (const float*)d_in[3];
    const float* sw1  = (const float*)d_in[4];
    const float* sw2  = (const float*)d_in[5];
    const float* bilW = (const float*)d_in[6];
    const float* w0   = (const float*)d_in[7];
    const float* b0   = (const float*)d_in[8];
    const float* g0   = (const float*)d_in[9];
    const float* be0  = (const float*)d_in[10];
    const float* w1   = (const float*)d_in[11];
    const float* b1   = (const float*)d_in[12];
    const float* g1   = (const float*)d_in[13];
    const float* be1  = (const float*)d_in[14];
    const float* w2   = (const float*)d_in[15];
    const float* b2   = (const float*)d_in[16];
    float* out = (float*)d_out;

    float *E2r, *E2x, *WT, *comb, *h0, *h0t, *h1, *w0t, *w1t, *lin, *sc0, *sh0, *sc1, *sh1;
    cudaGetSymbolAddress((void**)&E2r,  g_E2r);
    cudaGetSymbolAddress((void**)&E2x,  g_E2x);
    cudaGetSymbolAddress((void**)&WT,   g_WT);
    cudaGetSymbolAddress((void**)&comb, g_comb);
    cudaGetSymbolAddress((void**)&h0,   g_h0);
    cudaGetSymbolAddress((void**)&h0t,  g_h0t);
    cudaGetSymbolAddress((void**)&h1,   g_h1);
    cudaGetSymbolAddress((void**)&w0t,  g_w0t);
    cudaGetSymbolAddress((void**)&w1t,  g_w1t);
    cudaGetSymbolAddress((void**)&lin,  g_lin);
    cudaGetSymbolAddress((void**)&sc0,  g_scale0);
    cudaGetSymbolAddress((void**)&sh0,  g_shift0);
    cudaGetSymbolAddress((void**)&sc1,  g_scale1);
    cudaGetSymbolAddress((void**)&sh1,  g_shift1);

    transposeW_kernel<<<(FD * FD) / 256, 256>>>(bilW, WT);
    cvt_kernel<<<(COMB * H0N) / 1024, 256>>>(w0, w0t);
    cvt_kernel<<<(H0N * H1N) / 1024, 256>>>(w1, w1t);
    gather_se_kernel<<<BB, 256>>>(x, emb, lint, sw1, sw2, E2r, E2x, lin);
    // G1: comb = (E2r @ WT) * E2x scattered into [p|q] layout, tf32-rounded
    tf32gemm3_kernel<false, true><<<dim3(2 * BB / 128, FD / 128), 256>>>(
        E2r, WT, comb, 2 * BB, FD, FD, nullptr, E2x);
    // G2: h0 = comb @ w0t + b0
    tf32gemm3_kernel<true, false><<<dim3(BB / 128, H0N / 128), 256>>>(
        comb, w0t, h0, BB, H0N, COMB, b0, nullptr);
    bn_stats_kernel<<<H0N / 32, 512>>>(h0, H0N, g0, be0, sc0, sh0);
    bnrelu_kernel<<<(BB * H0N) / 1024, 256>>>(h0, sc0, sh0, h0t);
    // G3: h1 = h0t @ w1t + b1
    tf32gemm3_kernel<true, false><<<dim3(BB / 128, H1N / 128), 256>>>(
        h0t, w1t, h1, BB, H1N, H0N, b1, nullptr);
    bn_stats_kernel<<<H1N / 32, 512>>>(h1, H1N, g1, be1, sc1, sh1);
    final_kernel<<<BB / 8, 256>>>(h1, sc1, sh1, w2, b2, lin, bias, out);
}